// round 14
// baseline (speedup 1.0000x reference)
#include <cuda_runtime.h>
#include <cuda_fp16.h>
#include <cstdint>

#define N_IMG 64
#define C_IN  64
#define H_IN  56
#define W_IN  56
#define HW_IN (H_IN * W_IN)
#define K_OUT 128
#define H_OUT 54
#define W_OUT 54
#define PQ    (H_OUT * W_OUT)          /* 2916   */
#define NPQ   (N_IMG * PQ)             /* 186624 */

#define M_TILE 128
#define NCTA   (NPQ / M_TILE)          /* 1458 exact */
#define NTAPS  9

#define LDA_B 144                       /* A row stride bytes              */
#define LDB_B 272                       /* B row stride bytes              */
#define LDO   132                       /* epilogue staging stride, floats */

#define A_BYTES (128 * LDA_B)           /* 18432 */
#define B_BYTES (64 * LDB_B)            /* 17408 */
#define STAGE   (A_BYTES + B_BYTES)     /* 35840 */
#define OFF_STG 2048
#define SMEM_TOTAL (OFF_STG + 2 * STAGE)   /* 73728 */

/* x as NHWC fp16 (int8-valued, exact) */
__device__ __half g_xh[(size_t)N_IMG * H_IN * W_IN * C_IN];
/* weights [tap][c][ko] fp16 */
__device__ __half g_wh[NTAPS * C_IN * K_OUT];

__device__ __forceinline__ uint32_t smem_u32(const void* p) {
    uint32_t a;
    asm("{ .reg .u64 t; cvta.to.shared.u64 t, %1; cvt.u32.u64 %0, t; }"
        : "=r"(a) : "l"(p));
    return a;
}
#define CP16(dst, src) \
    asm volatile("cp.async.cg.shared.global [%0], [%1], 16;" \
                 :: "r"(dst), "l"(src) : "memory")
#define CP_COMMIT() asm volatile("cp.async.commit_group;" ::: "memory")
#define CP_WAIT0()  asm volatile("cp.async.wait_group 0;" ::: "memory")

__device__ __forceinline__ void ldsm4(uint32_t* r, uint32_t addr) {
    asm volatile("ldmatrix.sync.aligned.m8n8.x4.shared.b16 {%0,%1,%2,%3}, [%4];"
        : "=r"(r[0]), "=r"(r[1]), "=r"(r[2]), "=r"(r[3]) : "r"(addr));
}
__device__ __forceinline__ void ldsm4t(uint32_t* r, uint32_t addr) {
    asm volatile("ldmatrix.sync.aligned.m8n8.x4.trans.shared.b16 {%0,%1,%2,%3}, [%4];"
        : "=r"(r[0]), "=r"(r[1]), "=r"(r[2]), "=r"(r[3]) : "r"(addr));
}
/* fp16 accumulators: full-rate HMMA */
__device__ __forceinline__ void mma16816_f16(uint32_t* d, const uint32_t* a,
                                             const uint32_t* b) {
    asm volatile(
        "mma.sync.aligned.m16n8k16.row.col.f16.f16.f16.f16 "
        "{%0,%1}, {%2,%3,%4,%5}, {%6,%7}, {%0,%1};"
        : "+r"(d[0]), "+r"(d[1])
        : "r"(a[0]), "r"(a[1]), "r"(a[2]), "r"(a[3]), "r"(b[0]), "r"(b[1]));
}

/* ====== prep: clamp+trunc fp32 NCHW -> fp16 NHWC, + weight transform ====== */
__global__ void __launch_bounds__(256) prep_kernel(const float* __restrict__ x,
                                                   const float* __restrict__ w) {
    if (blockIdx.x >= N_IMG * H_IN) {
        int i = (blockIdx.x - N_IMG * H_IN) * 256 + threadIdx.x;
        int ko  = i & 127;
        int c   = (i >> 7) & 63;
        int tap = i >> 13;
        int r = tap / 3, s = tap - 3 * (tap / 3);
        g_wh[i] = __float2half_rn(w[((ko * C_IN + c) * 3 + r) * 3 + s]);
        return;
    }
    __shared__ __half tile[C_IN * 60];
    int np = blockIdx.x;
    int n = np / H_IN, p = np - n * H_IN;
    const float* src = x + (size_t)n * C_IN * HW_IN + p * W_IN;

    for (int i = threadIdx.x; i < 896; i += 256) {
        int c = i / 14, qg = i - c * 14;
        float4 v = *(const float4*)(src + c * HW_IN + qg * 4);
        union { __half h[4]; uint2 u; } pk;
        pk.h[0] = __float2half_rn((float)(int)fminf(fmaxf(v.x, -128.f), 127.f));
        pk.h[1] = __float2half_rn((float)(int)fminf(fmaxf(v.y, -128.f), 127.f));
        pk.h[2] = __float2half_rn((float)(int)fminf(fmaxf(v.z, -128.f), 127.f));
        pk.h[3] = __float2half_rn((float)(int)fminf(fmaxf(v.w, -128.f), 127.f));
        *(uint2*)&tile[c * 60 + qg * 4] = pk.u;
    }
    __syncthreads();

    uint4* dst = (uint4*)(g_xh + (size_t)np * (W_IN * C_IN));
    for (int i = threadIdx.x; i < 448; i += 256) {
        int q = i >> 3, c8 = i & 7;
        union { __half h[8]; uint4 u; } pk;
#pragma unroll
        for (int j = 0; j < 8; j++) pk.h[j] = tile[(c8 * 8 + j) * 60 + q];
        dst[q * 8 + c8] = pk.u;
    }
}

/* == main: full-rate fp16-acc HMMA, per-tap fp32 promotion ================= */
extern __shared__ unsigned char smem_raw[];

__global__ void __launch_bounds__(256, 2)
conv_kernel(const float* __restrict__ bias, float* __restrict__ out) {
    unsigned char* sm = smem_raw;
    int*   in_off  = (int*)sm;                 /* [128] NHWC element offset */
    int*   out_off = (int*)(sm + 512);         /* [128] */
    float* bias_s  = (float*)(sm + 1024);      /* [128] */
    const uint32_t smem_base = smem_u32(sm);
    const int tid  = threadIdx.x;
    const int lane = tid & 31;

    if (tid < 128) {
        int gm  = blockIdx.x * M_TILE + tid;
        int n   = gm / PQ;
        int rem = gm - n * PQ;
        int p   = rem / W_OUT;
        int q   = rem - p * W_OUT;
        in_off[tid]  = ((n * H_IN + p) * W_IN + q) * C_IN;
        out_off[tid] = n * (K_OUT * PQ) + rem;
        bias_s[tid]  = bias[tid];
    }
    __syncthreads();

    const int seg = tid & 7;                   /* A: 8 x 16B per pixel row */
    const int px0 = tid >> 3;
    const int bk  = tid >> 4;                  /* B: k-row base             */
    const int bc  = tid & 15;                  /* B: 16B chunk within k-row */

    auto load_stage = [&](int tap, int st) {
        uint32_t base = smem_base + OFF_STG + st * STAGE;
        int r = tap / 3, s = tap - 3 * (tap / 3);
        int tap_e = (r * W_IN + s) * C_IN;
        const unsigned char* xb = (const unsigned char*)g_xh;
#pragma unroll
        for (int j = 0; j < 4; j++) {
            int px = px0 + 32 * j;
            const void* src = xb + (size_t)(in_off[px] + tap_e) * 2 + seg * 16;
            CP16(base + px * LDA_B + seg * 16, src);
        }
        const unsigned char* wb =
            (const unsigned char*)(g_wh + tap * (C_IN * K_OUT));
#pragma unroll
        for (int j = 0; j < 4; j++) {
            int k = bk + 16 * j;
            CP16(base + A_BYTES + k * LDB_B + bc * 16, wb + k * 256 + bc * 16);
        }
    };

    const int warp_m = (tid >> 5) & 1;         /* 2 warps along M (64 rows) */
    const int warp_n = (tid >> 6);             /* 4 warps along N (32 cols) */
    const int m0 = warp_m * 64;
    const int n0 = warp_n * 32;

    /* per-thread ldmatrix base addresses (stage 0) */
    const uint32_t aBase0 = smem_base + OFF_STG
                          + (m0 + (lane & 15)) * LDA_B + (lane >> 4) * 16;
    const uint32_t bBase0 = smem_base + OFF_STG + A_BYTES
                          + (lane & 15) * LDB_B + (lane >> 4) * 16 + n0 * 2;

    float acc[4][4][4];                        /* fp32 master */
#pragma unroll
    for (int i = 0; i < 4; i++)
#pragma unroll
        for (int j = 0; j < 4; j++)
#pragma unroll
            for (int e = 0; e < 4; e++) acc[i][j][e] = 0.0f;

    load_stage(0, 0);
    CP_COMMIT();

    for (int t = 0; t < NTAPS; t++) {
        int st = t & 1;
        CP_WAIT0();                 /* stage st data landed                  */
        __syncthreads();            /* + all warps done with stage st^1 MMA */
        if (t < NTAPS - 1) {        /* prefetch t+1 overlaps MMA(t)          */
            load_stage(t + 1, st ^ 1);
            CP_COMMIT();
        }

        const uint32_t aB = aBase0 + st * STAGE;
        const uint32_t bB = bBase0 + st * STAGE;

        uint32_t hacc[4][4][2];     /* fp16 per-tap accumulators */
#pragma unroll
        for (int i = 0; i < 4; i++)
#pragma unroll
            for (int j = 0; j < 4; j++) {
                hacc[i][j][0] = 0u;
                hacc[i][j][1] = 0u;
            }

#pragma unroll
        for (int kk = 0; kk < 4; kk++) {
            uint32_t af[16], bf[8];
#pragma unroll
            for (int i = 0; i < 4; i++)
                ldsm4(&af[4 * i], aB + i * (16 * LDA_B) + kk * 32);
            ldsm4t(&bf[0], bB + kk * (16 * LDB_B));
            ldsm4t(&bf[4], bB + kk * (16 * LDB_B) + 32);
#pragma unroll
            for (int i = 0; i < 4; i++)
#pragma unroll
                for (int j = 0; j < 4; j++)
                    mma16816_f16(hacc[i][j], &af[4 * i], &bf[2 * j]);
        }

        /* promote per-tap fp16 partials into fp32 master */
#pragma unroll
        for (int i = 0; i < 4; i++)
#pragma unroll
            for (int j = 0; j < 4; j++) {
                float2 f0 = __half22float2(
                    *reinterpret_cast<__half2*>(&hacc[i][j][0]));
                float2 f1 = __half22float2(
                    *reinterpret_cast<__half2*>(&hacc[i][j][1]));
                acc[i][j][0] += f0.x;
                acc[i][j][1] += f0.y;
                acc[i][j][2] += f1.x;
                acc[i][j][3] += f1.y;
            }
    }
    __syncthreads();   /* all warps done reading smem before Os overwrite */

    /* ---- epilogue: stage [ko][m] fp32 in smem, coalesced NCHW stores ----- */
    float* Os = (float*)(sm + OFF_STG);
    {
        const int mrow = m0 + (lane >> 2);
        const int ncol = n0 + (lane & 3) * 2;
#pragma unroll
        for (int i = 0; i < 4; i++)
#pragma unroll
            for (int j = 0; j < 4; j++) {
                int m = mrow + i * 16;
                int n = ncol + j * 8;
                Os[n * LDO + m]           = acc[i][j][0];
                Os[(n + 1) * LDO + m]     = acc[i][j][1];
                Os[n * LDO + m + 8]       = acc[i][j][2];
                Os[(n + 1) * LDO + m + 8] = acc[i][j][3];
            }
    }
    __syncthreads();

#pragma unroll
    for (int j = 0; j < 64; j++) {
        int i  = tid + j * 256;
        int ko = i >> 7;
        int m  = i & 127;
        out[out_off[m] + ko * PQ] = Os[ko * LDO + m] + bias_s[ko];
    }
}

/* ========================================================================= */
extern "C" void kernel_launch(void* const* d_in, const int* in_sizes, int n_in,
                              void* d_out, int out_size) {
    const float* x    = (const float*)d_in[0];
    const float* w    = (const float*)d_in[1];
    const float* bias = (const float*)d_in[2];
    float* out = (float*)d_out;

    cudaFuncSetAttribute(conv_kernel,
                         cudaFuncAttributeMaxDynamicSharedMemorySize,
                         SMEM_TOTAL);

    prep_kernel<<<N_IMG * H_IN + 288, 256>>>(x, w);
    conv_kernel<<<NCTA, 256, SMEM_TOTAL>>>(bias, out);
}

// round 15
// speedup vs baseline: 1.0841x; 1.0841x over previous
#include <cuda_runtime.h>
#include <cuda_fp16.h>
#include <cstdint>

#define N_IMG 64
#define C_IN  64
#define H_IN  56
#define W_IN  56
#define HW_IN (H_IN * W_IN)
#define K_OUT 128
#define H_OUT 54
#define W_OUT 54
#define PQ    (H_OUT * W_OUT)          /* 2916   */
#define NPQ   (N_IMG * PQ)             /* 186624 */

#define M_TILE 128
#define NCTA   (NPQ / M_TILE)          /* 1458 exact */
#define NTAPS  9

#define LDA_B 144                       /* A row stride bytes              */
#define LDB_B 272                       /* B row stride bytes              */
#define LDO   132                       /* epilogue staging stride, floats */

#define A_BYTES (128 * LDA_B)           /* 18432 */
#define B_BYTES (64 * LDB_B)            /* 17408 */
#define STAGE   (A_BYTES + B_BYTES)     /* 35840 */
#define OFF_STG 2048
#define SMEM_TOTAL (OFF_STG + 2 * STAGE)   /* 73728 */

/* x as NHWC fp16 (int8-valued, exact) */
__device__ __half g_xh[(size_t)N_IMG * H_IN * W_IN * C_IN];
/* weights [tap][c][ko] fp16 */
__device__ __half g_wh[NTAPS * C_IN * K_OUT];

__device__ __forceinline__ uint32_t smem_u32(const void* p) {
    uint32_t a;
    asm("{ .reg .u64 t; cvta.to.shared.u64 t, %1; cvt.u32.u64 %0, t; }"
        : "=r"(a) : "l"(p));
    return a;
}
#define CP16(dst, src) \
    asm volatile("cp.async.cg.shared.global [%0], [%1], 16;" \
                 :: "r"(dst), "l"(src) : "memory")
#define CP_COMMIT() asm volatile("cp.async.commit_group;" ::: "memory")
#define CP_WAIT0()  asm volatile("cp.async.wait_group 0;" ::: "memory")

__device__ __forceinline__ void ldsm4(uint32_t* r, uint32_t addr) {
    asm volatile("ldmatrix.sync.aligned.m8n8.x4.shared.b16 {%0,%1,%2,%3}, [%4];"
        : "=r"(r[0]), "=r"(r[1]), "=r"(r[2]), "=r"(r[3]) : "r"(addr));
}
__device__ __forceinline__ void ldsm4t(uint32_t* r, uint32_t addr) {
    asm volatile("ldmatrix.sync.aligned.m8n8.x4.trans.shared.b16 {%0,%1,%2,%3}, [%4];"
        : "=r"(r[0]), "=r"(r[1]), "=r"(r[2]), "=r"(r[3]) : "r"(addr));
}
__device__ __forceinline__ void mma16816(float* d, const uint32_t* a,
                                         const uint32_t* b) {
    asm volatile(
        "mma.sync.aligned.m16n8k16.row.col.f32.f16.f16.f32 "
        "{%0,%1,%2,%3}, {%4,%5,%6,%7}, {%8,%9}, {%0,%1,%2,%3};"
        : "+f"(d[0]), "+f"(d[1]), "+f"(d[2]), "+f"(d[3])
        : "r"(a[0]), "r"(a[1]), "r"(a[2]), "r"(a[3]), "r"(b[0]), "r"(b[1]));
}

/* ====== prep: clamp+trunc fp32 NCHW -> fp16 NHWC, + weight transform ====== */
__global__ void __launch_bounds__(256) prep_kernel(const float* __restrict__ x,
                                                   const float* __restrict__ w) {
    if (blockIdx.x >= N_IMG * H_IN) {
        int i = (blockIdx.x - N_IMG * H_IN) * 256 + threadIdx.x;
        int ko  = i & 127;
        int c   = (i >> 7) & 63;
        int tap = i >> 13;
        int r = tap / 3, s = tap - 3 * (tap / 3);
        g_wh[i] = __float2half_rn(w[((ko * C_IN + c) * 3 + r) * 3 + s]);
        return;
    }
    __shared__ __half tile[C_IN * 60];
    int np = blockIdx.x;
    int n = np / H_IN, p = np - n * H_IN;
    const float* src = x + (size_t)n * C_IN * HW_IN + p * W_IN;

    for (int i = threadIdx.x; i < 896; i += 256) {
        int c = i / 14, qg = i - c * 14;
        float4 v = *(const float4*)(src + c * HW_IN + qg * 4);
        union { __half h[4]; uint2 u; } pk;
        pk.h[0] = __float2half_rn((float)(int)fminf(fmaxf(v.x, -128.f), 127.f));
        pk.h[1] = __float2half_rn((float)(int)fminf(fmaxf(v.y, -128.f), 127.f));
        pk.h[2] = __float2half_rn((float)(int)fminf(fmaxf(v.z, -128.f), 127.f));
        pk.h[3] = __float2half_rn((float)(int)fminf(fmaxf(v.w, -128.f), 127.f));
        *(uint2*)&tile[c * 60 + qg * 4] = pk.u;
    }
    __syncthreads();

    uint4* dst = (uint4*)(g_xh + (size_t)np * (W_IN * C_IN));
    for (int i = threadIdx.x; i < 448; i += 256) {
        int q = i >> 3, c8 = i & 7;
        union { __half h[8]; uint4 u; } pk;
#pragma unroll
        for (int j = 0; j < 8; j++) pk.h[j] = tile[(c8 * 8 + j) * 60 + q];
        dst[q * 8 + c8] = pk.u;
    }
}

/* == main: raw mma.sync HMMA f32-acc, warp-staggered kk to de-phase pipes == */
extern __shared__ unsigned char smem_raw[];

__global__ void __launch_bounds__(256, 2)
conv_kernel(const float* __restrict__ bias, float* __restrict__ out) {
    unsigned char* sm = smem_raw;
    int*   in_off  = (int*)sm;                 /* [128] NHWC element offset */
    int*   out_off = (int*)(sm + 512);         /* [128] */
    float* bias_s  = (float*)(sm + 1024);      /* [128] */
    const uint32_t smem_base = smem_u32(sm);
    const int tid  = threadIdx.x;
    const int lane = tid & 31;
    const int wid  = tid >> 5;

    if (tid < 128) {
        int gm  = blockIdx.x * M_TILE + tid;
        int n   = gm / PQ;
        int rem = gm - n * PQ;
        int p   = rem / W_OUT;
        int q   = rem - p * W_OUT;
        in_off[tid]  = ((n * H_IN + p) * W_IN + q) * C_IN;
        out_off[tid] = n * (K_OUT * PQ) + rem;
        bias_s[tid]  = bias[tid];
    }
    __syncthreads();

    const int seg = tid & 7;                   /* A: 8 x 16B per pixel row */
    const int px0 = tid >> 3;
    const int bk  = tid >> 4;                  /* B: k-row base             */
    const int bc  = tid & 15;                  /* B: 16B chunk within k-row */

    auto load_stage = [&](int tap, int st) {
        uint32_t base = smem_base + OFF_STG + st * STAGE;
        int r = tap / 3, s = tap - 3 * (tap / 3);
        int tap_e = (r * W_IN + s) * C_IN;
        const unsigned char* xb = (const unsigned char*)g_xh;
#pragma unroll
        for (int j = 0; j < 4; j++) {
            int px = px0 + 32 * j;
            const void* src = xb + (size_t)(in_off[px] + tap_e) * 2 + seg * 16;
            CP16(base + px * LDA_B + seg * 16, src);
        }
        const unsigned char* wb =
            (const unsigned char*)(g_wh + tap * (C_IN * K_OUT));
#pragma unroll
        for (int j = 0; j < 4; j++) {
            int k = bk + 16 * j;
            CP16(base + A_BYTES + k * LDB_B + bc * 16, wb + k * 256 + bc * 16);
        }
    };

    const int warp_m = wid & 1;                /* 2 warps along M (64 rows) */
    const int warp_n = wid >> 1;               /* 4 warps along N (32 cols) */
    const int m0 = warp_m * 64;
    const int n0 = warp_n * 32;
    const int woff = wid & 3;                  /* kk-rotation: de-phase warps */

    /* per-thread ldmatrix base addresses (stage 0) */
    const uint32_t aBase0 = smem_base + OFF_STG
                          + (m0 + (lane & 15)) * LDA_B + (lane >> 4) * 16;
    const uint32_t bBase0 = smem_base + OFF_STG + A_BYTES
                          + (lane & 15) * LDB_B + (lane >> 4) * 16 + n0 * 2;

    float acc[4][4][4];
#pragma unroll
    for (int i = 0; i < 4; i++)
#pragma unroll
        for (int j = 0; j < 4; j++)
#pragma unroll
            for (int e = 0; e < 4; e++) acc[i][j][e] = 0.0f;

    load_stage(0, 0);
    CP_COMMIT();

    for (int t = 0; t < NTAPS; t++) {
        int st = t & 1;
        CP_WAIT0();                 /* stage st data landed                  */
        __syncthreads();            /* + all warps done with stage st^1 MMA */
        if (t < NTAPS - 1) {        /* prefetch t+1 overlaps MMA(t)          */
            load_stage(t + 1, st ^ 1);
            CP_COMMIT();
        }

        const uint32_t aB = aBase0 + st * STAGE;
        const uint32_t bB = bBase0 + st * STAGE;

        uint32_t af[2][16], bf[2][8];
        /* prime this warp's first kk (rotated by woff) */
        {
            const int kk0 = woff;
#pragma unroll
            for (int i = 0; i < 4; i++)
                ldsm4(&af[0][4 * i], aB + i * (16 * LDA_B) + kk0 * 32);
            ldsm4t(&bf[0][0], bB + kk0 * (16 * LDB_B));
            ldsm4t(&bf[0][4], bB + kk0 * (16 * LDB_B) + 32);
        }

#pragma unroll
        for (int kkk = 0; kkk < 4; kkk++) {
            const int cur = kkk & 1, nxt = cur ^ 1;
            if (kkk < 3) {          /* prefetch next rotated kk during MMAs  */
                const int kkn = (kkk + 1 + woff) & 3;
#pragma unroll
                for (int i = 0; i < 4; i++)
                    ldsm4(&af[nxt][4 * i],
                          aB + i * (16 * LDA_B) + kkn * 32);
                ldsm4t(&bf[nxt][0], bB + kkn * (16 * LDB_B));
                ldsm4t(&bf[nxt][4], bB + kkn * (16 * LDB_B) + 32);
            }
#pragma unroll
            for (int i = 0; i < 4; i++)
#pragma unroll
                for (int j = 0; j < 4; j++)
                    mma16816(acc[i][j], &af[cur][4 * i], &bf[cur][2 * j]);
        }
    }
    __syncthreads();   /* all warps done reading smem before Os overwrite */

    /* ---- epilogue: stage [ko][m] fp32 in smem, coalesced NCHW stores ----- */
    float* Os = (float*)(sm + OFF_STG);
    {
        const int mrow = m0 + (lane >> 2);
        const int ncol = n0 + (lane & 3) * 2;
#pragma unroll
        for (int i = 0; i < 4; i++)
#pragma unroll
            for (int j = 0; j < 4; j++) {
                int m = mrow + i * 16;
                int n = ncol + j * 8;
                Os[n * LDO + m]           = acc[i][j][0];
                Os[(n + 1) * LDO + m]     = acc[i][j][1];
                Os[n * LDO + m + 8]       = acc[i][j][2];
                Os[(n + 1) * LDO + m + 8] = acc[i][j][3];
            }
    }
    __syncthreads();

#pragma unroll
    for (int j = 0; j < 64; j++) {
        int i  = tid + j * 256;
        int ko = i >> 7;
        int m  = i & 127;
        out[out_off[m] + ko * PQ] = Os[ko * LDO + m] + bias_s[ko];
    }
}

/* ========================================================================= */
extern "C" void kernel_launch(void* const* d_in, const int* in_sizes, int n_in,
                              void* d_out, int out_size) {
    const float* x    = (const float*)d_in[0];
    const float* w    = (const float*)d_in[1];
    const float* bias = (const float*)d_in[2];
    float* out = (float*)d_out;

    cudaFuncSetAttribute(conv_kernel,
                         cudaFuncAttributeMaxDynamicSharedMemorySize,
                         SMEM_TOTAL);

    prep_kernel<<<N_IMG * H_IN + 288, 256>>>(x, w);
    conv_kernel<<<NCTA, 256, SMEM_TOTAL>>>(bias, out);
}